// round 1
// baseline (speedup 1.0000x reference)
#include <cuda_runtime.h>
#include <cstdint>

// Problem constants
#define N_TOKENS 131072
#define EMBED    64
#define NCODES   1024

// Main kernel tiling
#define TILE_T   128
#define TILE_K   64
#define NTHREADS 256
#define E_STRIDE 68   // padded code-tile row stride (floats), 16B-aligned rows

#define LOSS_TOK_PER_BLK 64
#define NBLK_LOSS (N_TOKENS / LOSS_TOK_PER_BLK)   // 2048

// Scratch (allocation-free: __device__ globals)
__device__ float  g_esq[NCODES];
__device__ int    g_hist[NCODES];
__device__ double g_partial[NBLK_LOSS];

// ---- f32x2 helpers (bitwise-identical to scalar fp32 FFMA, 2x throughput) ----
#define PACKDUP(dst, f) \
    asm("mov.b64 %0, {%1, %1};" : "=l"(dst) : "r"(__float_as_uint(f)))
#define UNPACK2(lo, hi, v) \
    asm("mov.b64 {%0, %1}, %2;" : "=f"(lo), "=f"(hi) : "l"(v))
#define FMA2(d, a, b, c) \
    asm("fma.rn.f32x2 %0, %1, %2, %3;" : "=l"(d) : "l"(a), "l"(b), "l"(c))

// -------------------------------------------------------------------------
// Kernel 0: e_sq per code + zero histogram (re-run every replay for determinism)
// -------------------------------------------------------------------------
__global__ void vq_prep(const float* __restrict__ cb)
{
    int k = blockIdx.x * blockDim.x + threadIdx.x;
    if (k < NCODES) {
        const float* r = cb + (size_t)k * EMBED;
        float s = 0.f;
        #pragma unroll
        for (int d = 0; d < EMBED; ++d) s += r[d] * r[d];
        g_esq[k]  = s;
        g_hist[k] = 0;
    }
}

// -------------------------------------------------------------------------
// Kernel 1: fused distance + argmin.
//   score_k = (z_sq - 2*dot_k) + e_sq_k   (replicates reference fp32 rounding)
//   argmin with first-index tie-break (strict < scan, idx tie-break on merge)
// -------------------------------------------------------------------------
extern __shared__ float s_dyn[];

__global__ void __launch_bounds__(NTHREADS, 2)
vq_argmin(const float* __restrict__ z, const float* __restrict__ cb,
          float* __restrict__ out)
{
    float* sz  = s_dyn;                    // [64][128]  z tile, transposed
    float* se  = sz + EMBED * TILE_T;      // [64][68]   code tile, transposed
    float* szq = se + EMBED * E_STRIDE;    // [128]      z_sq per token

    const int tid   = threadIdx.x;
    const int tbase = blockIdx.x * TILE_T;

    // Load z tile transposed: sz[d][t] = z[tbase+t][d]
    for (int i = tid; i < EMBED * TILE_T; i += NTHREADS) {
        int t = i & (TILE_T - 1);
        int d = i >> 7;
        sz[d * TILE_T + t] = z[(size_t)(tbase + t) * EMBED + d];
    }
    __syncthreads();

    if (tid < TILE_T) {
        float s = 0.f;
        for (int d = 0; d < EMBED; ++d) {
            float v = sz[d * TILE_T + tid];
            s += v * v;
        }
        szq[tid] = s;
    }
    __syncthreads();

    const int t0 = (tid >> 3) * 4;      // 4 tokens per thread
    const int c0 = (tid & 7) * 8;       // 8 codes per thread (as 4 pairs)

    float zqr[4];
    #pragma unroll
    for (int i = 0; i < 4; ++i) zqr[i] = szq[t0 + i];

    float best[4];
    int   bidx[4];
    #pragma unroll
    for (int i = 0; i < 4; ++i) { best[i] = 3.4e38f; bidx[i] = 0; }

    for (int kt = 0; kt < NCODES / TILE_K; ++kt) {
        const int kb = kt * TILE_K;

        // Load code tile transposed: se[d][c] = cb[kb+c][d]  (coalesced gmem)
        for (int i = tid; i < TILE_K * EMBED; i += NTHREADS) {
            int d = i & 63;
            int c = i >> 6;
            se[d * E_STRIDE + c] = cb[(size_t)(kb + c) * EMBED + d];
        }
        __syncthreads();

        unsigned long long acc[4][4];   // [token][code-pair], f32x2 accumulators
        #pragma unroll
        for (int i = 0; i < 4; ++i)
            #pragma unroll
            for (int p = 0; p < 4; ++p) acc[i][p] = 0ULL;

        #pragma unroll 8
        for (int d = 0; d < EMBED; ++d) {
            float4 zv = *(const float4*)(sz + d * TILE_T + t0);
            ulonglong2 eA = *(const ulonglong2*)(se + d * E_STRIDE + c0);
            ulonglong2 eB = *(const ulonglong2*)(se + d * E_STRIDE + c0 + 4);

            unsigned long long zp0, zp1, zp2, zp3;
            PACKDUP(zp0, zv.x);
            PACKDUP(zp1, zv.y);
            PACKDUP(zp2, zv.z);
            PACKDUP(zp3, zv.w);

            FMA2(acc[0][0], zp0, eA.x, acc[0][0]);
            FMA2(acc[0][1], zp0, eA.y, acc[0][1]);
            FMA2(acc[0][2], zp0, eB.x, acc[0][2]);
            FMA2(acc[0][3], zp0, eB.y, acc[0][3]);
            FMA2(acc[1][0], zp1, eA.x, acc[1][0]);
            FMA2(acc[1][1], zp1, eA.y, acc[1][1]);
            FMA2(acc[1][2], zp1, eB.x, acc[1][2]);
            FMA2(acc[1][3], zp1, eB.y, acc[1][3]);
            FMA2(acc[2][0], zp2, eA.x, acc[2][0]);
            FMA2(acc[2][1], zp2, eA.y, acc[2][1]);
            FMA2(acc[2][2], zp2, eB.x, acc[2][2]);
            FMA2(acc[2][3], zp2, eB.y, acc[2][3]);
            FMA2(acc[3][0], zp3, eA.x, acc[3][0]);
            FMA2(acc[3][1], zp3, eA.y, acc[3][1]);
            FMA2(acc[3][2], zp3, eB.x, acc[3][2]);
            FMA2(acc[3][3], zp3, eB.y, acc[3][3]);
        }

        // Epilogue: score + running argmin (codes scanned in ascending k)
        #pragma unroll
        for (int i = 0; i < 4; ++i) {
            float zq = zqr[i];
            #pragma unroll
            for (int p = 0; p < 4; ++p) {
                float lo, hi;
                UNPACK2(lo, hi, acc[i][p]);
                int k0 = kb + c0 + 2 * p;
                float t1 = fmaf(-2.f, lo, zq);   // RN(zq - 2*dot), 2*dot exact
                float s0 = t1 + g_esq[k0];
                if (s0 < best[i]) { best[i] = s0; bidx[i] = k0; }
                float t2 = fmaf(-2.f, hi, zq);
                float s1 = t2 + g_esq[k0 + 1];
                if (s1 < best[i]) { best[i] = s1; bidx[i] = k0 + 1; }
            }
        }
        __syncthreads();
    }

    // Reduce across the 8 code-column lanes; tie -> smaller index (= first occurrence)
    #pragma unroll
    for (int i = 0; i < 4; ++i) {
        float b = best[i];
        int   x = bidx[i];
        #pragma unroll
        for (int off = 4; off; off >>= 1) {
            float b2 = __shfl_down_sync(0xffffffffu, b, off);
            int   x2 = __shfl_down_sync(0xffffffffu, x, off);
            if (b2 < b || (b2 == b && x2 < x)) { b = b2; x = x2; }
        }
        if ((tid & 7) == 0)
            out[(size_t)N_TOKENS * EMBED + tbase + t0 + i] = (float)x;
    }
}

// -------------------------------------------------------------------------
// Kernel 2: gather z_q, write straight-through output, MSE partial sums,
//           histogram. Deterministic per-block double reduction.
// -------------------------------------------------------------------------
__global__ void __launch_bounds__(256)
vq_loss(const float* __restrict__ z, const float* __restrict__ cb,
        float* __restrict__ out)
{
    __shared__ double sred[256];
    const int tid   = threadIdx.x;
    const int token = blockIdx.x * LOSS_TOK_PER_BLK + (tid >> 2);
    const int part  = tid & 3;

    const int idx = (int)out[(size_t)N_TOKENS * EMBED + token];

    const float* cp = cb  + (size_t)idx   * EMBED + part * 16;
    const float* zp = z   + (size_t)token * EMBED + part * 16;
    float*       op = out + (size_t)token * EMBED + part * 16;

    double acc = 0.0;
    #pragma unroll
    for (int q = 0; q < 4; ++q) {
        float4 e  = *(const float4*)(cp + q * 4);
        float4 zv = *(const float4*)(zp + q * 4);
        float dx = e.x - zv.x, dy = e.y - zv.y, dz = e.z - zv.z, dw = e.w - zv.w;
        float4 st = make_float4(zv.x + dx, zv.y + dy, zv.z + dz, zv.w + dw);
        *(float4*)(op + q * 4) = st;
        acc += (double)(dx * dx) + (double)(dy * dy)
             + (double)(dz * dz) + (double)(dw * dw);
    }

    sred[tid] = acc;
    __syncthreads();
    #pragma unroll
    for (int off = 128; off; off >>= 1) {
        if (tid < off) sred[tid] += sred[tid + off];
        __syncthreads();
    }
    if (tid == 0) g_partial[blockIdx.x] = sred[0];

    if (part == 0) atomicAdd(&g_hist[idx], 1);
}

// -------------------------------------------------------------------------
// Kernel 3: finalize scalars
// -------------------------------------------------------------------------
__global__ void __launch_bounds__(1024)
vq_final(float* __restrict__ out)
{
    __shared__ double sred[1024];
    __shared__ double s_loss;
    const int tid = threadIdx.x;

    sred[tid] = g_partial[tid] + g_partial[tid + 1024];
    __syncthreads();
    #pragma unroll
    for (int off = 512; off; off >>= 1) {
        if (tid < off) sred[tid] += sred[tid + off];
        __syncthreads();
    }
    if (tid == 0) s_loss = sred[0];
    __syncthreads();

    // entropy terms: p = c/n + 1e-10 (fp32, per reference), sum p*log(p)
    {
        float p = (float)g_hist[tid] / 131072.0f + 1e-10f;
        sred[tid] = (double)(p * logf(p));
    }
    __syncthreads();
    #pragma unroll
    for (int off = 512; off; off >>= 1) {
        if (tid < off) sred[tid] += sred[tid + off];
        __syncthreads();
    }

    if (tid == 0) {
        const size_t base = (size_t)N_TOKENS * EMBED + N_TOKENS;
        float cl      = (float)(s_loss / (double)((size_t)N_TOKENS * EMBED));
        float commit  = 0.25f * cl;
        float entropy = (float)(-sred[0]);
        float eloss   = -0.1f * (entropy / 6.9314718055994531f);
        float perp    = expf(entropy);
        out[base + 0] = cl;
        out[base + 1] = commit;
        out[base + 2] = eloss;
        out[base + 3] = perp;
    }
}

// -------------------------------------------------------------------------
extern "C" void kernel_launch(void* const* d_in, const int* in_sizes, int n_in,
                              void* d_out, int out_size)
{
    const float* z  = (const float*)d_in[0];   // z_e      [131072, 64]
    const float* cb = (const float*)d_in[1];   // codebook [1024, 64]
    float* out = (float*)d_out;

    const int smem_bytes = (EMBED * TILE_T + EMBED * E_STRIDE + TILE_T) * 4; // 50688
    static bool attr_set = false;
    if (!attr_set) {
        cudaFuncSetAttribute(vq_argmin,
                             cudaFuncAttributeMaxDynamicSharedMemorySize,
                             smem_bytes);
        attr_set = true;
    }

    vq_prep<<<(NCODES + 255) / 256, 256>>>(cb);
    vq_argmin<<<N_TOKENS / TILE_T, NTHREADS, smem_bytes>>>(z, cb, out);
    vq_loss<<<NBLK_LOSS, 256>>>(z, cb, out);
    vq_final<<<1, 1024>>>(out);
}